// round 4
// baseline (speedup 1.0000x reference)
#include <cuda_runtime.h>
#include <math.h>

// Problem shape (fixed by the dataset)
#define BB 16
#define CC 2
#define TT 2000
#define FF 257
#define NCHUNK 40
#define CL 50          // TT / NCHUNK
#define NBLK (BB * NCHUNK)

#define PLANE  (TT * FF)        // complex elements per (b,c) plane = 514000
#define PLANE4 (PLANE / 2)      // float4 elements per plane        = 257000
#define N4     (BB * CC * PLANE4)  // total float4s in input/res    = 8224000

// Scratch (no cudaMalloc allowed)
__device__ float          g_agg[NBLK * FF];   // chunk-local aggregates
__device__ volatile int   g_flag[NBLK];       // publish flags
__device__ unsigned int   g_vid;              // dynamic block ticket

__global__ void init_kernel() {
    int i = threadIdx.x;
    if (i < NBLK) g_flag[i] = 0;
    if (i == 0) g_vid = 0;
}

// ---------------------------------------------------------------------------
// Kernel A: EMA scan with decoupled lookback. Writes smooth (sqrt of state)
// and s_final only. Light on stores; ch0 phase-3 re-read hits L2.
// ---------------------------------------------------------------------------
__global__ void __launch_bounds__(288, 5)
scan_kernel(const float* __restrict__ in,
            const float* __restrict__ s1,
            const float* __restrict__ alpha_p,
            float* __restrict__ s_final,
            float* __restrict__ smooth) {
    __shared__ unsigned int s_vid;
    if (threadIdx.x == 0) s_vid = atomicAdd(&g_vid, 1u);
    __syncthreads();
    unsigned int vid = s_vid;
    int b = vid / NCHUNK;
    int chunk = vid % NCHUNK;

    int f = threadIdx.x;
    bool active = (f < FF);
    int fc = active ? f : 0;

    float alpha = 1.0f / (1.0f + expf(-alpha_p[fc]));
    float r = 1.0f - alpha;

    const float2* in0 = (const float2*)in + (size_t)(b * CC + 0) * PLANE;
    int t0 = chunk * CL;

    // Phase 1: chunk-local scan from 0 (batched loads for MLP)
    float s = 0.0f;
    if (active) {
        const float2* p = in0 + (size_t)t0 * FF + fc;
        for (int tt = 0; tt < CL; tt += 10) {
            float2 x[10];
#pragma unroll
            for (int j = 0; j < 10; ++j) x[j] = p[(size_t)(tt + j) * FF];
#pragma unroll
            for (int j = 0; j < 10; ++j) {
                float d = x[j].x * x[j].x + x[j].y * x[j].y;
                s = fmaf(r, s, alpha * d);
            }
        }
        g_agg[(size_t)vid * FF + fc] = s;
    }
    __syncthreads();
    __threadfence();
    if (threadIdx.x == 0) g_flag[vid] = 1;   // release

    // Lookback
    if (threadIdx.x == 0 && chunk > 0) {
        int base = b * NCHUNK;
        for (int c = 0; c < chunk; ++c)
            while (g_flag[base + c] == 0) { }
        __threadfence();                      // acquire
    }
    __syncthreads();

    float rL = 1.0f;
#pragma unroll
    for (int i = 0; i < CL; ++i) rL *= r;     // r^CL

    float prefix = s1[b * FF + fc];
    {
        const float* agg = g_agg + (size_t)(b * NCHUNK) * FF + fc;
        for (int c = 0; c < chunk; ++c)
            prefix = fmaf(rL, prefix, agg[(size_t)c * FF]);
    }

    // Phase 3: corrected scan, write smooth only (ch0 re-read is L2-hit)
    if (active) {
        float* sm_out = smooth + (size_t)b * PLANE;
        float sacc = prefix;
#pragma unroll 5
        for (int t = t0; t < t0 + CL; ++t) {
            size_t idx = (size_t)t * FF + fc;
            float2 x0 = __ldcs(&in0[idx]);
            float d0 = x0.x * x0.x + x0.y * x0.y;
            sacc = fmaf(r, sacc, alpha * d0);
            sm_out[idx] = sqrtf(sacc);        // plain store: keep in L2 for B
        }
        if (chunk == NCHUNK - 1) s_final[b * FF + fc] = sacc;
    }
}

// ---------------------------------------------------------------------------
// Kernel B: pure elementwise, flat float4 streaming. No serial dependence.
// res = input / (cat + 1e-8) * weights + bias, where cat is smooth (c=0) or
// per-element magnitude (c=1).
// ---------------------------------------------------------------------------
__global__ void __launch_bounds__(256)
elem_kernel(const float4* __restrict__ in4,
            const float* __restrict__ smooth,
            const float* __restrict__ weights,
            const float* __restrict__ bias,
            float4* __restrict__ res4) {
    int stride = gridDim.x * blockDim.x;
    for (int i4 = blockIdx.x * blockDim.x + threadIdx.x; i4 < N4; i4 += stride) {
        int pl  = i4 / PLANE4;          // (b,c) plane index
        int w4  = i4 - pl * PLANE4;     // float4 index within plane
        int c   = pl & 1;
        int b   = pl >> 1;
        int p0  = w4 * 2;               // complex index within plane
        int f0  = p0 % FF;
        int f1  = f0 + 1 == FF ? 0 : f0 + 1;

        float4 x = __ldcs(&in4[i4]);    // (re0, im0, re1, im1)
        float w_0 = __ldg(&weights[c * FF + f0]);
        float w_1 = __ldg(&weights[c * FF + f1]);
        float b_0 = __ldg(&bias[c * FF + f0]);
        float b_1 = __ldg(&bias[c * FF + f1]);

        float m0, m1;
        if (c == 0) {
            float2 sm = *(const float2*)(smooth + (size_t)b * PLANE + p0);
            m0 = sm.x; m1 = sm.y;
        } else {
            m0 = sqrtf(x.x * x.x + x.y * x.y);
            m1 = sqrtf(x.z * x.z + x.w * x.w);
        }
        float i0 = w_0 / (m0 + 1e-8f);
        float i1 = w_1 / (m1 + 1e-8f);

        float4 o;
        o.x = fmaf(x.x, i0, b_0);
        o.y = fmaf(x.y, i0, b_0);
        o.z = fmaf(x.z, i1, b_1);
        o.w = fmaf(x.w, i1, b_1);
        __stcs(&res4[i4], o);
    }
}

extern "C" void kernel_launch(void* const* d_in, const int* in_sizes, int n_in,
                              void* d_out, int out_size) {
    // metadata order: input, s_1, weights, bias, alpha_param
    const float* in = (const float*)d_in[0];
    const float* s1 = (const float*)d_in[1];
    const float* w  = (const float*)d_in[2];
    const float* bi = (const float*)d_in[3];
    const float* ap = (const float*)d_in[4];

    float* out = (float*)d_out;
    float* res     = out;                                        // [B,C,T,F,2]
    float* s_final = out + (size_t)BB * CC * TT * FF * 2;        // [B,1,F,1]
    float* smooth  = s_final + (size_t)BB * FF;                  // [B,1,T,F,1]

    init_kernel<<<1, NBLK>>>();
    scan_kernel<<<NBLK, 288>>>(in, s1, ap, s_final, smooth);

    int blocks = (N4 + 256 * 8 - 1) / (256 * 8);                 // ~4016 blocks
    elem_kernel<<<blocks, 256>>>((const float4*)in, smooth, w, bi, (float4*)res);
}

// round 5
// speedup vs baseline: 1.0220x; 1.0220x over previous
#include <cuda_runtime.h>
#include <math.h>

// Problem shape (fixed by the dataset)
#define BB 16
#define CC 2
#define TT 2000
#define FF 257
#define NCHUNK 40
#define CL 50          // TT / NCHUNK
#define NBLK (BB * NCHUNK)
#define PLANE (TT * FF)

// Scratch (no cudaMalloc allowed). Zero-initialized at module load;
// self-reset at end of every kernel run keeps graph replays correct.
__device__ float          g_agg[NBLK * FF];   // chunk-local aggregates
__device__ volatile int   g_flag[NBLK];       // publish flags
__device__ unsigned int   g_vid;              // dynamic block ticket
__device__ unsigned int   g_done;             // completion counter

__device__ __forceinline__ float sqrt_approx(float x) {
    float y;
    asm("sqrt.approx.f32 %0, %1;" : "=f"(y) : "f"(x));
    return y;
}
__device__ __forceinline__ float rcp_approx(float x) {
    float y;
    asm("rcp.approx.f32 %0, %1;" : "=f"(y) : "f"(x));
    return y;
}

__global__ void __launch_bounds__(288, 4)
fused_kernel(const float* __restrict__ in,
             const float* __restrict__ s1,
             const float* __restrict__ weights,
             const float* __restrict__ bias,
             const float* __restrict__ alpha_p,
             float* __restrict__ res,
             float* __restrict__ s_final,
             float* __restrict__ smooth) {
    __shared__ unsigned int s_vid;
    if (threadIdx.x == 0) s_vid = atomicAdd(&g_vid, 1u);
    __syncthreads();
    unsigned int vid = s_vid;
    int b = vid / NCHUNK;
    int chunk = vid % NCHUNK;

    int f = threadIdx.x;
    bool active = (f < FF);
    int fc = active ? f : 0;   // clamp so inactive lanes stay convergent

    float alpha = 1.0f / (1.0f + expf(-alpha_p[fc]));
    float r = 1.0f - alpha;

    const float2* in0 = (const float2*)in + (size_t)(b * CC + 0) * PLANE;
    int t0 = chunk * CL;

    // ---------------- Phase 1: chunk-local scan from 0 (batched loads) ------
    float s = 0.0f;
    if (active) {
        const float2* p = in0 + (size_t)t0 * FF + fc;
        for (int tt = 0; tt < CL; tt += 10) {
            float2 x[10];
#pragma unroll
            for (int j = 0; j < 10; ++j) x[j] = p[(size_t)(tt + j) * FF];
#pragma unroll
            for (int j = 0; j < 10; ++j) {
                float d = x[j].x * x[j].x + x[j].y * x[j].y;
                s = fmaf(r, s, alpha * d);
            }
        }
        g_agg[(size_t)vid * FF + fc] = s;
    }
    __syncthreads();
    __threadfence();
    if (threadIdx.x == 0) g_flag[vid] = 1;   // release

    // ---------------- Lookback: parallel spin, then fold ---------------------
    if (threadIdx.x < chunk) {
        int base = b * NCHUNK;
        while (g_flag[base + threadIdx.x] == 0) { }
    }
    __syncthreads();
    __threadfence();                          // acquire

    float rL = 1.0f;
#pragma unroll
    for (int i = 0; i < CL; ++i) rL *= r;     // r^CL

    float prefix = s1[b * FF + fc];
    {
        const float* agg = g_agg + (size_t)(b * NCHUNK) * FF + fc;
        for (int c = 0; c < chunk; ++c)
            prefix = fmaf(rL, prefix, agg[(size_t)c * FF]);
    }

    // ---------------- Phase 3: corrected scan + fused elementwise ------------
    if (active) {
        float w0 = weights[0 * FF + fc], w1 = weights[1 * FF + fc];
        float b0 = bias[0 * FF + fc],    b1 = bias[1 * FF + fc];

        const float2* in1 = (const float2*)in + (size_t)(b * CC + 1) * PLANE;
        float2* res0 = (float2*)res + (size_t)(b * CC + 0) * PLANE;
        float2* res1 = (float2*)res + (size_t)(b * CC + 1) * PLANE;
        float* sm_out = smooth + (size_t)b * PLANE;

        float sacc = prefix;
        for (int tt = 0; tt < CL; tt += 5) {
            size_t base_idx = (size_t)(t0 + tt) * FF + fc;
            float2 x0[5], x1[5];
#pragma unroll
            for (int j = 0; j < 5; ++j) x0[j] = __ldcs(&in0[base_idx + (size_t)j * FF]);
#pragma unroll
            for (int j = 0; j < 5; ++j) x1[j] = __ldcs(&in1[base_idx + (size_t)j * FF]);
#pragma unroll
            for (int j = 0; j < 5; ++j) {
                size_t idx = base_idx + (size_t)j * FF;
                float d0 = x0[j].x * x0[j].x + x0[j].y * x0[j].y;
                sacc = fmaf(r, sacc, alpha * d0);
                float sm = sqrt_approx(sacc);
                __stcs(&sm_out[idx], sm);

                float inv0 = w0 * rcp_approx(sm + 1e-8f);
                float m1 = sqrt_approx(x1[j].x * x1[j].x + x1[j].y * x1[j].y);
                float inv1 = w1 * rcp_approx(m1 + 1e-8f);

                __stcs(&res0[idx], make_float2(fmaf(x0[j].x, inv0, b0),
                                               fmaf(x0[j].y, inv0, b0)));
                __stcs(&res1[idx], make_float2(fmaf(x1[j].x, inv1, b1),
                                               fmaf(x1[j].y, inv1, b1)));
            }
        }
        if (chunk == NCHUNK - 1) s_final[b * FF + fc] = sacc;
    }

    // ---------------- Self-reset for next graph replay -----------------------
    __syncthreads();
    if (threadIdx.x == 0) {
        unsigned int old = atomicAdd(&g_done, 1u);
        if (old == NBLK - 1) {                // last block: reset everything
            for (int i = 0; i < NBLK; ++i) g_flag[i] = 0;
            g_vid = 0;
            g_done = 0;
            __threadfence();
        }
    }
}

extern "C" void kernel_launch(void* const* d_in, const int* in_sizes, int n_in,
                              void* d_out, int out_size) {
    // metadata order: input, s_1, weights, bias, alpha_param
    const float* in = (const float*)d_in[0];
    const float* s1 = (const float*)d_in[1];
    const float* w  = (const float*)d_in[2];
    const float* bi = (const float*)d_in[3];
    const float* ap = (const float*)d_in[4];

    float* out = (float*)d_out;
    float* res     = out;                                        // [B,C,T,F,2]
    float* s_final = out + (size_t)BB * CC * TT * FF * 2;        // [B,1,F,1]
    float* smooth  = s_final + (size_t)BB * FF;                  // [B,1,T,F,1]

    fused_kernel<<<NBLK, 288>>>(in, s1, w, bi, ap, res, s_final, smooth);
}